// round 1
// baseline (speedup 1.0000x reference)
#include <cuda_runtime.h>
#include <math.h>

#define D   128
#define S   (D*D*D)
#define TS  12            // tile row stride (padded for bank-conflict-free LDS)
#define TZN 10            // tile z extent (8 + 2 halo)
#define TILE_N (TZN*TS*TS) // 1440

__global__ __launch_bounds__(512) void dem_pass(
    const float* __restrict__ posx, const float* __restrict__ posy, const float* __restrict__ posz,
    const float* __restrict__ v0x,  const float* __restrict__ v0y,  const float* __restrict__ v0z,
    const float* __restrict__ v1x,  const float* __restrict__ v1y,  const float* __restrict__ v1z,
    const float* __restrict__ cpx,  const float* __restrict__ cpy,  const float* __restrict__ cpz,
    const float* __restrict__ cvx,  const float* __restrict__ cvy,  const float* __restrict__ cvz,
    const float* __restrict__ maskp,
    float* __restrict__ outx, float* __restrict__ outy, float* __restrict__ outz,
    float ETA, float DTPM, float GPM)
{
    __shared__ float4 t4[TILE_N];   // x, y, z, vx
    __shared__ float2 t2[TILE_N];   // vy, vz

    const int tx = threadIdx.x, ty = threadIdx.y, tz = threadIdx.z;
    const int tid = (tz*8 + ty)*8 + tx;
    const int x0 = blockIdx.x*8, y0 = blockIdx.y*8, z0 = blockIdx.z*8;
    const int idx = ((z0+tz)*D + (y0+ty))*D + (x0+tx);

    const float xn  = cpx[idx], yn  = cpy[idx], zn  = cpz[idx];
    const float vxn = cvx[idx], vyn = cvy[idx], vzn = cvz[idx];

    const float KN = 6.0e6f, PS = 0.1f, KN_PS = 6.0e5f;

    float fx = 0.f, fy = 0.f, fz = 0.f;

    #pragma unroll
    for (int m = 0; m < 2; ++m) {
        const float* px = posx + m*S;
        const float* py = posy + m*S;
        const float* pz = posz + m*S;
        const float* wx = m ? v1x : v0x;
        const float* wy = m ? v1y : v0y;
        const float* wz = m ? v1z : v0z;

        if (m) __syncthreads();   // protect tile reuse between phases

        for (int s = tid; s < TILE_N; s += 512) {
            int lz = s / (TS*TS);
            int r  = s - lz*(TS*TS);
            int ly = r / TS;
            int lx = r - ly*TS;
            int gz = (z0 + lz - 1) & (D-1);
            int gy = (y0 + ly - 1) & (D-1);
            int gx = (x0 + lx - 1) & (D-1);
            int g  = (gz*D + gy)*D + gx;
            t4[s] = make_float4(px[g], py[g], pz[g], wx[g]);
            t2[s] = make_float2(wy[g], wz[g]);
        }
        __syncthreads();

        const int base = (tz+1)*(TS*TS) + (ty+1)*TS + (tx+1);
        #pragma unroll
        for (int dz = -1; dz <= 1; ++dz)
        #pragma unroll
        for (int dy = -1; dy <= 1; ++dy)
        #pragma unroll
        for (int dx = -1; dx <= 1; ++dx) {
            int j = base + dz*(TS*TS) + dy*TS + dx;
            float4 p4 = t4[j];
            float2 p2 = t2[j];
            float ddx = xn - p4.x;
            float ddy = yn - p4.y;
            float ddz = zn - p4.z;
            // fold the reference's max(d2, 1e-12) into the fma chain:
            // self-term (ddx=ddy=ddz=0) yields exactly 1e-12, same as the clamp.
            float d2   = fmaf(ddx, ddx, fmaf(ddy, ddy, fmaf(ddz, ddz, 1e-12f)));
            float inv  = rsqrtf(d2);
            float dist = d2 * inv;                 // = sqrt(d2)
            float rdc  = fminf(inv, 1e4f);         // = 1 / max(dist, 1e-4)
            float dvx = vxn - p4.w;
            float dvy = vyn - p2.x;
            float dvz = vzn - p2.y;
            float dot = fmaf(dvx, ddx, fmaf(dvy, ddy, dvz*ddz));
            float coef = fmaf(ETA*dot, rdc, fmaf(KN, dist, -KN_PS)) * rdc;
            coef = (dist < PS) ? coef : 0.0f;
            fx = fmaf(coef, ddx, fx);
            fy = fmaf(coef, ddy, fy);
            fz = fmaf(coef, ddz, fz);
        }
    }

    const float mk = maskp[idx];

    // boundary forces (mask factor folded into the outer mk multiply)
    float fbx = 0.f, fby = 0.f, fbz = 0.f;
    {
        if (xn > 0.1f && xn < 0.15f) fbx = fmaf(KN, 0.15f - xn, -ETA*vxn);
        if (xn > 12.65f)             fbx = fmaf(-KN, xn - 12.65f, -ETA*vxn);
        if (yn > 0.1f && yn < 0.15f) fby = fmaf(KN, 0.15f - yn, -ETA*vyn);
        if (yn > 12.65f)             fby = fmaf(-KN, yn - 12.65f, -ETA*vyn);
        if (zn > 0.1f && zn < 0.15f) fbz = fmaf(KN, 0.15f - zn, -ETA*vzn);
        if (zn > 12.65f)             fbz = fmaf(-KN, zn - 12.65f, -ETA*vzn);
    }

    outx[idx] = fmaf(DTPM*mk, fbx - fx, vxn);
    outy[idx] = fmaf(DTPM*mk, fby - fy, vyn);
    outz[idx] = fmaf(DTPM*mk, GPM - fz + fbz, vzn);
}

extern "C" void kernel_launch(void* const* d_in, const int* in_sizes, int n_in,
                              void* d_out, int out_size)
{
    const float* x  = (const float*)d_in[0];
    const float* y  = (const float*)d_in[1];
    const float* z  = (const float*)d_in[2];
    const float* vx = (const float*)d_in[3];
    const float* vy = (const float*)d_in[4];
    const float* vz = (const float*)d_in[5];
    const float* mk = (const float*)d_in[6];
    float* out = (float*)d_out;

    // physics constants computed in double on host
    const double PM    = 4.0/3.0*3.1415*0.001*2700.0;           // particle mass
    const double alpha = 0.6931471805599453/3.141592653589793;  // ln2/pi
    const double gamma = alpha / sqrt(alpha*alpha + 1.0);
    const float ETA  = (float)(2.0 * gamma * sqrt(6.0e6 * PM));
    const float DTPM = (float)(1e-4 / PM);
    const float GPM  = (float)(-9.8 * PM);

    dim3 blk(8,8,8), grd(16,16,16);
    const int Sl = S;

    // out layout: [3 components][2 layers][S]
    float* ox0 = out + 0*2*Sl;  float* ox1 = ox0 + Sl;
    float* oy0 = out + 1*2*Sl;  float* oy1 = oy0 + Sl;
    float* oz0 = out + 2*2*Sl;  float* oz1 = oz0 + Sl;

    // pass n = 0: all velocities original
    dem_pass<<<grd, blk>>>(x, y, z,
                           vx, vy, vz,                 // m=0 vel (layer 0 orig)
                           vx+Sl, vy+Sl, vz+Sl,        // m=1 vel (layer 1 orig)
                           x, y, z,                    // center positions (layer 0)
                           vx, vy, vz,                 // center velocities (layer 0)
                           mk,
                           ox0, oy0, oz0,
                           ETA, DTPM, GPM);

    // pass n = 1: layer-0 velocities are the just-updated outputs
    dem_pass<<<grd, blk>>>(x, y, z,
                           ox0, oy0, oz0,              // m=0 vel (layer 0 UPDATED)
                           vx+Sl, vy+Sl, vz+Sl,        // m=1 vel (layer 1 orig)
                           x+Sl, y+Sl, z+Sl,           // center positions (layer 1)
                           vx+Sl, vy+Sl, vz+Sl,        // center velocities (layer 1 orig)
                           mk+Sl,
                           ox1, oy1, oz1,
                           ETA, DTPM, GPM);
}

// round 2
// speedup vs baseline: 1.0625x; 1.0625x over previous
#include <cuda_runtime.h>
#include <math.h>

#define D   128
#define S   (D*D*D)
#define ROW   20           // tile x stride (floats), 18 used
#define PLANE 200          // ROW * 10 (y extent)
#define TILE_N 2000        // PLANE * 10 (z extent)
#define TILE_USED 1800     // 10*10*18 actually loaded

typedef unsigned long long u64;

__device__ __forceinline__ u64 f2add(u64 a, u64 b){u64 r; asm("add.rn.f32x2 %0,%1,%2;":"=l"(r):"l"(a),"l"(b)); return r;}
__device__ __forceinline__ u64 f2mul(u64 a, u64 b){u64 r; asm("mul.rn.f32x2 %0,%1,%2;":"=l"(r):"l"(a),"l"(b)); return r;}
__device__ __forceinline__ u64 f2fma(u64 a, u64 b, u64 c){u64 r; asm("fma.rn.f32x2 %0,%1,%2,%3;":"=l"(r):"l"(a),"l"(b),"l"(c)); return r;}
__device__ __forceinline__ u64 f2pack(float lo, float hi){u64 r; asm("mov.b64 %0,{%1,%2};":"=l"(r):"f"(lo),"f"(hi)); return r;}
__device__ __forceinline__ void f2unpack(u64 a, float& lo, float& hi){asm("mov.b64 {%0,%1},%2;":"=f"(lo),"=f"(hi):"l"(a));}
__device__ __forceinline__ u64 f2mid(u64 a, u64 b){
    float al, ah, bl, bh; f2unpack(a, al, ah); f2unpack(b, bl, bh); return f2pack(ah, bl);
}

__global__ __launch_bounds__(512, 2) void dem_pass(
    const float* __restrict__ posx, const float* __restrict__ posy, const float* __restrict__ posz,
    const float* __restrict__ v0x,  const float* __restrict__ v0y,  const float* __restrict__ v0z,
    const float* __restrict__ v1x,  const float* __restrict__ v1y,  const float* __restrict__ v1z,
    const float* __restrict__ cpx,  const float* __restrict__ cpy,  const float* __restrict__ cpz,
    const float* __restrict__ cvx,  const float* __restrict__ cvy,  const float* __restrict__ cvz,
    const float* __restrict__ maskp,
    float* __restrict__ outx, float* __restrict__ outy, float* __restrict__ outz,
    float ETA, float DTPM, float GPM)
{
    __shared__ __align__(16) float sh[6][TILE_N];

    const int tx = threadIdx.x, ty = threadIdx.y, tz = threadIdx.z;
    const int tid = (tz*8 + ty)*8 + tx;
    const int x0 = blockIdx.x*16, y0 = blockIdx.y*8, z0 = blockIdx.z*8;
    const int idx = ((z0+tz)*D + (y0+ty))*D + (x0 + 2*tx);

    // --- precompute loader slots (shared across both phases) ---
    int gsl[4], ssl[4];
    #pragma unroll
    for (int i = 0; i < 4; ++i) {
        int e = tid + i*512;
        int lz = e / 180;
        int r  = e - lz*180;
        int ly = r / 18;
        int lx = r - ly*18;
        int gz = (z0 + lz - 1) & (D-1);
        int gy = (y0 + ly - 1) & (D-1);
        int gx = (x0 + lx - 1) & (D-1);
        gsl[i] = (gz*D + gy)*D + gx;
        ssl[i] = lz*PLANE + ly*ROW + lx;
    }

    // --- packed centers (negated so all inner subs become adds) ---
    const u64 SGN = 0x8000000080000000ull;
    const u64 xnp  = *(const u64*)(cpx + idx);
    const u64 ynp  = *(const u64*)(cpy + idx);
    const u64 znp  = *(const u64*)(cpz + idx);
    const u64 vxnp = *(const u64*)(cvx + idx);
    const u64 vynp = *(const u64*)(cvy + idx);
    const u64 vznp = *(const u64*)(cvz + idx);
    const u64 nxn  = xnp  ^ SGN, nyn  = ynp  ^ SGN, nzn  = znp  ^ SGN;
    const u64 nvxn = vxnp ^ SGN, nvyn = vynp ^ SGN, nvzn = vznp ^ SGN;

    const u64 EPS2 = f2pack(1e-12f, 1e-12f);
    const u64 NKN  = f2pack(-6.0e6f, -6.0e6f);
    const u64 KNPS = f2pack( 6.0e5f,  6.0e5f);
    const u64 NETA = f2pack(-ETA, -ETA);

    u64 fx = 0ull, fy = 0ull, fz = 0ull;   // packed accumulators (match reference sign)

    const int base = (tz+1)*PLANE + (ty+1)*ROW + (2*tx + 1);   // odd x offset

    auto body = [&](u64 px_, u64 py_, u64 pz_, u64 wx_, u64 wy_, u64 wz_) {
        u64 ddx = f2add(px_, nxn);
        u64 ddy = f2add(py_, nyn);
        u64 ddz = f2add(pz_, nzn);
        u64 d2  = f2fma(ddx, ddx, f2fma(ddy, ddy, f2fma(ddz, ddz, EPS2)));
        float d2l, d2h; f2unpack(d2, d2l, d2h);
        float invl = rsqrtf(d2l), invh = rsqrtf(d2h);
        float rl = (d2l < 0.01f) ? fminf(invl, 1e4f) : 0.0f;   // gate folded into rdc
        float rh = (d2h < 0.01f) ? fminf(invh, 1e4f) : 0.0f;
        u64 inv  = f2pack(invl, invh);
        u64 rdc  = f2pack(rl, rh);
        u64 dist = f2mul(d2, inv);
        u64 dvx = f2add(wx_, nvxn);
        u64 dvy = f2add(wy_, nvyn);
        u64 dvz = f2add(wz_, nvzn);
        u64 dot = f2fma(dvx, ddx, f2fma(dvy, ddy, f2mul(dvz, ddz)));
        u64 s   = f2fma(NKN, dist, KNPS);
        s       = f2fma(f2mul(NETA, dot), rdc, s);
        u64 nc  = f2mul(s, rdc);             // = -coef ; ddx = -(xn-p) => product matches ref
        fx = f2fma(nc, ddx, fx);
        fy = f2fma(nc, ddy, fy);
        fz = f2fma(nc, ddz, fz);
    };

    #pragma unroll
    for (int m = 0; m < 2; ++m) {
        const float* px = posx + m*S;
        const float* py = posy + m*S;
        const float* pz = posz + m*S;
        const float* wx = m ? v1x : v0x;
        const float* wy = m ? v1y : v0y;
        const float* wz = m ? v1z : v0z;

        if (m) __syncthreads();
        #pragma unroll
        for (int i = 0; i < 4; ++i) {
            if (i < 3 || tid < TILE_USED - 3*512) {
                int g = gsl[i], s2 = ssl[i];
                sh[0][s2] = px[g];  sh[1][s2] = py[g];  sh[2][s2] = pz[g];
                sh[3][s2] = wx[g];  sh[4][s2] = wy[g];  sh[5][s2] = wz[g];
            }
        }
        __syncthreads();

        #pragma unroll
        for (int dz = -1; dz <= 1; ++dz)
        #pragma unroll
        for (int dy = -1; dy <= 1; ++dy) {
            const int rb = base + dz*PLANE + dy*ROW;
            // dx = -1 pair starts at even offset rb-1 ; dx = +1 pair at even rb+1
            u64 Ax = *(const u64*)(&sh[0][rb-1]);
            u64 Ay = *(const u64*)(&sh[1][rb-1]);
            u64 Az = *(const u64*)(&sh[2][rb-1]);
            u64 Au = *(const u64*)(&sh[3][rb-1]);
            u64 Av = *(const u64*)(&sh[4][rb-1]);
            u64 Aw = *(const u64*)(&sh[5][rb-1]);
            body(Ax, Ay, Az, Au, Av, Aw);
            u64 Bx = *(const u64*)(&sh[0][rb+1]);
            u64 By = *(const u64*)(&sh[1][rb+1]);
            u64 Bz = *(const u64*)(&sh[2][rb+1]);
            u64 Bu = *(const u64*)(&sh[3][rb+1]);
            u64 Bv = *(const u64*)(&sh[4][rb+1]);
            u64 Bw = *(const u64*)(&sh[5][rb+1]);
            body(Bx, By, Bz, Bu, Bv, Bw);
            body(f2mid(Ax,Bx), f2mid(Ay,By), f2mid(Az,Bz),
                 f2mid(Au,Bu), f2mid(Av,Bv), f2mid(Aw,Bw));
        }
    }

    // --- epilogue: boundary + velocity update, scalar per cell ---
    const float KN = 6.0e6f;
    float xn0, xn1, yn0, yn1, zn0, zn1;
    float vx0, vx1, vy0, vy1, vz0, vz1;
    float fx0, fx1, fy0, fy1, fz0, fz1;
    f2unpack(xnp, xn0, xn1);  f2unpack(ynp, yn0, yn1);  f2unpack(znp, zn0, zn1);
    f2unpack(vxnp, vx0, vx1); f2unpack(vynp, vy0, vy1); f2unpack(vznp, vz0, vz1);
    f2unpack(fx, fx0, fx1);   f2unpack(fy, fy0, fy1);   f2unpack(fz, fz0, fz1);
    const u64 mkp = *(const u64*)(maskp + idx);
    float mk0, mk1; f2unpack(mkp, mk0, mk1);

    float2 ox, oy, oz;
    {
        float fbx = 0.f, fby = 0.f, fbz = 0.f;
        if (xn0 > 0.1f && xn0 < 0.15f) fbx = fmaf(KN, 0.15f - xn0, -ETA*vx0);
        if (xn0 > 12.65f)              fbx = fmaf(-KN, xn0 - 12.65f, -ETA*vx0);
        if (yn0 > 0.1f && yn0 < 0.15f) fby = fmaf(KN, 0.15f - yn0, -ETA*vy0);
        if (yn0 > 12.65f)              fby = fmaf(-KN, yn0 - 12.65f, -ETA*vy0);
        if (zn0 > 0.1f && zn0 < 0.15f) fbz = fmaf(KN, 0.15f - zn0, -ETA*vz0);
        if (zn0 > 12.65f)              fbz = fmaf(-KN, zn0 - 12.65f, -ETA*vz0);
        ox.x = fmaf(DTPM*mk0, fbx - fx0, vx0);
        oy.x = fmaf(DTPM*mk0, fby - fy0, vy0);
        oz.x = fmaf(DTPM*mk0, GPM - fz0 + fbz, vz0);
    }
    {
        float fbx = 0.f, fby = 0.f, fbz = 0.f;
        if (xn1 > 0.1f && xn1 < 0.15f) fbx = fmaf(KN, 0.15f - xn1, -ETA*vx1);
        if (xn1 > 12.65f)              fbx = fmaf(-KN, xn1 - 12.65f, -ETA*vx1);
        if (yn1 > 0.1f && yn1 < 0.15f) fby = fmaf(KN, 0.15f - yn1, -ETA*vy1);
        if (yn1 > 12.65f)              fby = fmaf(-KN, yn1 - 12.65f, -ETA*vy1);
        if (zn1 > 0.1f && zn1 < 0.15f) fbz = fmaf(KN, 0.15f - zn1, -ETA*vz1);
        if (zn1 > 12.65f)              fbz = fmaf(-KN, zn1 - 12.65f, -ETA*vz1);
        ox.y = fmaf(DTPM*mk1, fbx - fx1, vx1);
        oy.y = fmaf(DTPM*mk1, fby - fy1, vy1);
        oz.y = fmaf(DTPM*mk1, GPM - fz1 + fbz, vz1);
    }
    *(float2*)(outx + idx) = ox;
    *(float2*)(outy + idx) = oy;
    *(float2*)(outz + idx) = oz;
}

extern "C" void kernel_launch(void* const* d_in, const int* in_sizes, int n_in,
                              void* d_out, int out_size)
{
    const float* x  = (const float*)d_in[0];
    const float* y  = (const float*)d_in[1];
    const float* z  = (const float*)d_in[2];
    const float* vx = (const float*)d_in[3];
    const float* vy = (const float*)d_in[4];
    const float* vz = (const float*)d_in[5];
    const float* mk = (const float*)d_in[6];
    float* out = (float*)d_out;

    const double PM    = 4.0/3.0*3.1415*0.001*2700.0;
    const double alpha = 0.6931471805599453/3.141592653589793;
    const double gamma = alpha / sqrt(alpha*alpha + 1.0);
    const float ETA  = (float)(2.0 * gamma * sqrt(6.0e6 * PM));
    const float DTPM = (float)(1e-4 / PM);
    const float GPM  = (float)(-9.8 * PM);

    dim3 blk(8,8,8), grd(8,16,16);
    const int Sl = S;

    float* ox0 = out + 0*2*Sl;  float* ox1 = ox0 + Sl;
    float* oy0 = out + 1*2*Sl;  float* oy1 = oy0 + Sl;
    float* oz0 = out + 2*2*Sl;  float* oz1 = oz0 + Sl;

    // pass n = 0: all velocities original
    dem_pass<<<grd, blk>>>(x, y, z,
                           vx, vy, vz,
                           vx+Sl, vy+Sl, vz+Sl,
                           x, y, z,
                           vx, vy, vz,
                           mk,
                           ox0, oy0, oz0,
                           ETA, DTPM, GPM);

    // pass n = 1: layer-0 velocities are the just-updated outputs
    dem_pass<<<grd, blk>>>(x, y, z,
                           ox0, oy0, oz0,
                           vx+Sl, vy+Sl, vz+Sl,
                           x+Sl, y+Sl, z+Sl,
                           vx+Sl, vy+Sl, vz+Sl,
                           mk+Sl,
                           ox1, oy1, oz1,
                           ETA, DTPM, GPM);
}

// round 3
// speedup vs baseline: 1.1182x; 1.0524x over previous
#include <cuda_runtime.h>
#include <math.h>

#define D   128
#define S   (D*D*D)
#define ROW   20           // tile x stride (floats), 18 used
#define PLANE 200          // ROW * 10 (y extent)
#define TILEZ 6            // 4 + 2 halo
#define TILE_N 1200        // PLANE * TILEZ
#define TILE_USED 1080     // 6*10*18 actually loaded

typedef unsigned long long u64;

__device__ __forceinline__ u64 f2add(u64 a, u64 b){u64 r; asm("add.rn.f32x2 %0,%1,%2;":"=l"(r):"l"(a),"l"(b)); return r;}
__device__ __forceinline__ u64 f2mul(u64 a, u64 b){u64 r; asm("mul.rn.f32x2 %0,%1,%2;":"=l"(r):"l"(a),"l"(b)); return r;}
__device__ __forceinline__ u64 f2fma(u64 a, u64 b, u64 c){u64 r; asm("fma.rn.f32x2 %0,%1,%2,%3;":"=l"(r):"l"(a),"l"(b),"l"(c)); return r;}
__device__ __forceinline__ u64 f2pack(float lo, float hi){u64 r; asm("mov.b64 %0,{%1,%2};":"=l"(r):"f"(lo),"f"(hi)); return r;}
__device__ __forceinline__ void f2unpack(u64 a, float& lo, float& hi){asm("mov.b64 {%0,%1},%2;":"=f"(lo),"=f"(hi):"l"(a));}
__device__ __forceinline__ u64 f2mid(u64 a, u64 b){
    float al, ah, bl, bh; f2unpack(a, al, ah); f2unpack(b, bl, bh); return f2pack(ah, bl);
}

__global__ __launch_bounds__(256, 3) void dem_pass(
    const float* __restrict__ posx, const float* __restrict__ posy, const float* __restrict__ posz,
    const float* __restrict__ v0x,  const float* __restrict__ v0y,  const float* __restrict__ v0z,
    const float* __restrict__ v1x,  const float* __restrict__ v1y,  const float* __restrict__ v1z,
    const float* __restrict__ cpx,  const float* __restrict__ cpy,  const float* __restrict__ cpz,
    const float* __restrict__ cvx,  const float* __restrict__ cvy,  const float* __restrict__ cvz,
    const float* __restrict__ maskp,
    float* __restrict__ outx, float* __restrict__ outy, float* __restrict__ outz,
    float ETA, float DTPM, float GPM)
{
    __shared__ __align__(16) float sh[6][TILE_N];

    const int tx = threadIdx.x, ty = threadIdx.y, tz = threadIdx.z;
    const int tid = (tz*8 + ty)*8 + tx;
    const int x0 = blockIdx.x*16, y0 = blockIdx.y*8, z0 = blockIdx.z*4;
    const int idx = ((z0+tz)*D + (y0+ty))*D + (x0 + 2*tx);

    // --- packed centers, negated so all inner subtractions become adds ---
    const u64 SGN = 0x8000000080000000ull;
    const u64 nxn  = *(const u64*)(cpx + idx) ^ SGN;
    const u64 nyn  = *(const u64*)(cpy + idx) ^ SGN;
    const u64 nzn  = *(const u64*)(cpz + idx) ^ SGN;
    const u64 nvxn = *(const u64*)(cvx + idx) ^ SGN;
    const u64 nvyn = *(const u64*)(cvy + idx) ^ SGN;
    const u64 nvzn = *(const u64*)(cvz + idx) ^ SGN;

    const u64 EPS2 = f2pack(1e-12f, 1e-12f);
    const u64 NKN  = f2pack(-6.0e6f, -6.0e6f);
    const u64 KNPS = f2pack( 6.0e5f,  6.0e5f);
    const u64 NETA = f2pack(-ETA, -ETA);

    u64 fx = 0ull, fy = 0ull, fz = 0ull;   // packed force accumulators

    const int base = (tz+1)*PLANE + (ty+1)*ROW + (2*tx + 1);   // odd x offset

    auto body = [&](u64 px_, u64 py_, u64 pz_, u64 wx_, u64 wy_, u64 wz_) {
        u64 ddx = f2add(px_, nxn);
        u64 ddy = f2add(py_, nyn);
        u64 ddz = f2add(pz_, nzn);
        u64 d2  = f2fma(ddx, ddx, f2fma(ddy, ddy, f2fma(ddz, ddz, EPS2)));
        float d2l, d2h; f2unpack(d2, d2l, d2h);
        float invl = rsqrtf(d2l), invh = rsqrtf(d2h);
        float rl = (d2l < 0.01f) ? fminf(invl, 1e4f) : 0.0f;   // contact gate folded into rdc
        float rh = (d2h < 0.01f) ? fminf(invh, 1e4f) : 0.0f;
        u64 inv  = f2pack(invl, invh);
        u64 rdc  = f2pack(rl, rh);
        u64 dist = f2mul(d2, inv);
        u64 dvx = f2add(wx_, nvxn);
        u64 dvy = f2add(wy_, nvyn);
        u64 dvz = f2add(wz_, nvzn);
        u64 dot = f2fma(dvx, ddx, f2fma(dvy, ddy, f2mul(dvz, ddz)));
        u64 s   = f2fma(NKN, dist, KNPS);
        s       = f2fma(f2mul(NETA, dot), rdc, s);
        u64 nc  = f2mul(s, rdc);             // = -coef ; ddx = -(xn-p) => product matches ref
        fx = f2fma(nc, ddx, fx);
        fy = f2fma(nc, ddy, fy);
        fz = f2fma(nc, ddz, fz);
    };

    #pragma unroll
    for (int m = 0; m < 2; ++m) {
        const float* px = posx + m*S;
        const float* py = posy + m*S;
        const float* pz = posz + m*S;
        const float* wx = m ? v1x : v0x;
        const float* wy = m ? v1y : v0y;
        const float* wz = m ? v1z : v0z;

        if (m) __syncthreads();
        #pragma unroll
        for (int i = 0; i < 5; ++i) {
            int e = tid + i*256;
            if (i < 4 || e < TILE_USED) {
                int lz = e / 180;
                int r  = e - lz*180;
                int ly = r / 18;
                int lx = r - ly*18;
                int gz = (z0 + lz - 1) & (D-1);
                int gy = (y0 + ly - 1) & (D-1);
                int gx = (x0 + lx - 1) & (D-1);
                int g  = (gz*D + gy)*D + gx;
                int s2 = lz*PLANE + ly*ROW + lx;
                sh[0][s2] = px[g];  sh[1][s2] = py[g];  sh[2][s2] = pz[g];
                sh[3][s2] = wx[g];  sh[4][s2] = wy[g];  sh[5][s2] = wz[g];
            }
        }
        __syncthreads();

        #pragma unroll
        for (int dz = -1; dz <= 1; ++dz)
        #pragma unroll
        for (int dy = -1; dy <= 1; ++dy) {
            const int rb = base + dz*PLANE + dy*ROW;
            u64 Ax = *(const u64*)(&sh[0][rb-1]);
            u64 Ay = *(const u64*)(&sh[1][rb-1]);
            u64 Az = *(const u64*)(&sh[2][rb-1]);
            u64 Au = *(const u64*)(&sh[3][rb-1]);
            u64 Av = *(const u64*)(&sh[4][rb-1]);
            u64 Aw = *(const u64*)(&sh[5][rb-1]);
            body(Ax, Ay, Az, Au, Av, Aw);
            u64 Bx = *(const u64*)(&sh[0][rb+1]);
            u64 By = *(const u64*)(&sh[1][rb+1]);
            u64 Bz = *(const u64*)(&sh[2][rb+1]);
            u64 Bu = *(const u64*)(&sh[3][rb+1]);
            u64 Bv = *(const u64*)(&sh[4][rb+1]);
            u64 Bw = *(const u64*)(&sh[5][rb+1]);
            body(Bx, By, Bz, Bu, Bv, Bw);
            body(f2mid(Ax,Bx), f2mid(Ay,By), f2mid(Az,Bz),
                 f2mid(Au,Bu), f2mid(Av,Bv), f2mid(Aw,Bw));
        }
    }

    // --- epilogue: reload centers from gmem (frees registers across main loop) ---
    const float KN = 6.0e6f;
    float xn0, xn1, yn0, yn1, zn0, zn1;
    float vx0, vx1, vy0, vy1, vz0, vz1;
    float fx0, fx1, fy0, fy1, fz0, fz1;
    float mk0, mk1;
    f2unpack(*(const u64*)(cpx + idx), xn0, xn1);
    f2unpack(*(const u64*)(cpy + idx), yn0, yn1);
    f2unpack(*(const u64*)(cpz + idx), zn0, zn1);
    f2unpack(*(const u64*)(cvx + idx), vx0, vx1);
    f2unpack(*(const u64*)(cvy + idx), vy0, vy1);
    f2unpack(*(const u64*)(cvz + idx), vz0, vz1);
    f2unpack(*(const u64*)(maskp + idx), mk0, mk1);
    f2unpack(fx, fx0, fx1);   f2unpack(fy, fy0, fy1);   f2unpack(fz, fz0, fz1);

    float2 ox, oy, oz;
    {
        float fbx = 0.f, fby = 0.f, fbz = 0.f;
        if (xn0 > 0.1f && xn0 < 0.15f) fbx = fmaf(KN, 0.15f - xn0, -ETA*vx0);
        if (xn0 > 12.65f)              fbx = fmaf(-KN, xn0 - 12.65f, -ETA*vx0);
        if (yn0 > 0.1f && yn0 < 0.15f) fby = fmaf(KN, 0.15f - yn0, -ETA*vy0);
        if (yn0 > 12.65f)              fby = fmaf(-KN, yn0 - 12.65f, -ETA*vy0);
        if (zn0 > 0.1f && zn0 < 0.15f) fbz = fmaf(KN, 0.15f - zn0, -ETA*vz0);
        if (zn0 > 12.65f)              fbz = fmaf(-KN, zn0 - 12.65f, -ETA*vz0);
        ox.x = fmaf(DTPM*mk0, fbx - fx0, vx0);
        oy.x = fmaf(DTPM*mk0, fby - fy0, vy0);
        oz.x = fmaf(DTPM*mk0, GPM - fz0 + fbz, vz0);
    }
    {
        float fbx = 0.f, fby = 0.f, fbz = 0.f;
        if (xn1 > 0.1f && xn1 < 0.15f) fbx = fmaf(KN, 0.15f - xn1, -ETA*vx1);
        if (xn1 > 12.65f)              fbx = fmaf(-KN, xn1 - 12.65f, -ETA*vx1);
        if (yn1 > 0.1f && yn1 < 0.15f) fby = fmaf(KN, 0.15f - yn1, -ETA*vy1);
        if (yn1 > 12.65f)              fby = fmaf(-KN, yn1 - 12.65f, -ETA*vy1);
        if (zn1 > 0.1f && zn1 < 0.15f) fbz = fmaf(KN, 0.15f - zn1, -ETA*vz1);
        if (zn1 > 12.65f)              fbz = fmaf(-KN, zn1 - 12.65f, -ETA*vz1);
        ox.y = fmaf(DTPM*mk1, fbx - fx1, vx1);
        oy.y = fmaf(DTPM*mk1, fby - fy1, vy1);
        oz.y = fmaf(DTPM*mk1, GPM - fz1 + fbz, vz1);
    }
    *(float2*)(outx + idx) = ox;
    *(float2*)(outy + idx) = oy;
    *(float2*)(outz + idx) = oz;
}

extern "C" void kernel_launch(void* const* d_in, const int* in_sizes, int n_in,
                              void* d_out, int out_size)
{
    const float* x  = (const float*)d_in[0];
    const float* y  = (const float*)d_in[1];
    const float* z  = (const float*)d_in[2];
    const float* vx = (const float*)d_in[3];
    const float* vy = (const float*)d_in[4];
    const float* vz = (const float*)d_in[5];
    const float* mk = (const float*)d_in[6];
    float* out = (float*)d_out;

    const double PM    = 4.0/3.0*3.1415*0.001*2700.0;
    const double alpha = 0.6931471805599453/3.141592653589793;
    const double gamma = alpha / sqrt(alpha*alpha + 1.0);
    const float ETA  = (float)(2.0 * gamma * sqrt(6.0e6 * PM));
    const float DTPM = (float)(1e-4 / PM);
    const float GPM  = (float)(-9.8 * PM);

    dim3 blk(8,8,4), grd(8,16,32);
    const int Sl = S;

    float* ox0 = out + 0*2*Sl;  float* ox1 = ox0 + Sl;
    float* oy0 = out + 1*2*Sl;  float* oy1 = oy0 + Sl;
    float* oz0 = out + 2*2*Sl;  float* oz1 = oz0 + Sl;

    // pass n = 0: all velocities original
    dem_pass<<<grd, blk>>>(x, y, z,
                           vx, vy, vz,
                           vx+Sl, vy+Sl, vz+Sl,
                           x, y, z,
                           vx, vy, vz,
                           mk,
                           ox0, oy0, oz0,
                           ETA, DTPM, GPM);

    // pass n = 1: layer-0 velocities are the just-updated outputs
    dem_pass<<<grd, blk>>>(x, y, z,
                           ox0, oy0, oz0,
                           vx+Sl, vy+Sl, vz+Sl,
                           x+Sl, y+Sl, z+Sl,
                           vx+Sl, vy+Sl, vz+Sl,
                           mk+Sl,
                           ox1, oy1, oz1,
                           ETA, DTPM, GPM);
}

// round 4
// speedup vs baseline: 1.2411x; 1.1099x over previous
#include <cuda_runtime.h>
#include <math.h>

#define D   128
#define S   (D*D*D)
#define ROW   34           // tile x stride in floats (no pad needed: half-warp = 32 consecutive floats)
#define PLANE 340          // ROW * 10 (y extent 8 + 2 halo)
#define TILEZ 6            // 4 z cells + 2 halo
#define TILE_N 2040        // PLANE * TILEZ
// smem: 6 fields * 2040 * 4B = 48960 B  (<= 48KB static limit)

typedef unsigned long long u64;

__device__ __forceinline__ u64 f2add(u64 a, u64 b){u64 r; asm("add.rn.f32x2 %0,%1,%2;":"=l"(r):"l"(a),"l"(b)); return r;}
__device__ __forceinline__ u64 f2mul(u64 a, u64 b){u64 r; asm("mul.rn.f32x2 %0,%1,%2;":"=l"(r):"l"(a),"l"(b)); return r;}
__device__ __forceinline__ u64 f2fma(u64 a, u64 b, u64 c){u64 r; asm("fma.rn.f32x2 %0,%1,%2,%3;":"=l"(r):"l"(a),"l"(b),"l"(c)); return r;}
__device__ __forceinline__ u64 f2pack(float lo, float hi){u64 r; asm("mov.b64 %0,{%1,%2};":"=l"(r):"f"(lo),"f"(hi)); return r;}
__device__ __forceinline__ void f2unpack(u64 a, float& lo, float& hi){asm("mov.b64 {%0,%1},%2;":"=f"(lo),"=f"(hi):"l"(a));}
__device__ __forceinline__ u64 f2mid(u64 a, u64 b){
    float al, ah, bl, bh; f2unpack(a, al, ah); f2unpack(b, bl, bh); return f2pack(ah, bl);
}

__global__ __launch_bounds__(256, 2) void dem_pass(
    const float* __restrict__ posx, const float* __restrict__ posy, const float* __restrict__ posz,
    const float* __restrict__ v0x,  const float* __restrict__ v0y,  const float* __restrict__ v0z,
    const float* __restrict__ v1x,  const float* __restrict__ v1y,  const float* __restrict__ v1z,
    const float* __restrict__ cpx,  const float* __restrict__ cpy,  const float* __restrict__ cpz,
    const float* __restrict__ cvx,  const float* __restrict__ cvy,  const float* __restrict__ cvz,
    const float* __restrict__ maskp,
    float* __restrict__ outx, float* __restrict__ outy, float* __restrict__ outz,
    float ETA, float DTPM, float GPM)
{
    __shared__ __align__(16) float sh[6][TILE_N];

    const int tx = threadIdx.x, ty = threadIdx.y, tz = threadIdx.z;     // (16, 8, 2)
    const int tid = (tz*8 + ty)*16 + tx;
    const int x0 = blockIdx.x*32, y0 = blockIdx.y*8, z0 = blockIdx.z*4;
    const int zA = z0 + 2*tz;
    const int idxA = ((zA    )*D + (y0+ty))*D + (x0 + 2*tx);
    const int idxB = idxA + D*D;                                        // z + 1

    const u64 SGN = 0x8000000080000000ull;
    // packed negated centers for the two z-cells
    const u64 AnX  = *(const u64*)(cpx + idxA) ^ SGN;
    const u64 AnY  = *(const u64*)(cpy + idxA) ^ SGN;
    const u64 AnZ  = *(const u64*)(cpz + idxA) ^ SGN;
    const u64 AnVX = *(const u64*)(cvx + idxA) ^ SGN;
    const u64 AnVY = *(const u64*)(cvy + idxA) ^ SGN;
    const u64 AnVZ = *(const u64*)(cvz + idxA) ^ SGN;
    const u64 BnX  = *(const u64*)(cpx + idxB) ^ SGN;
    const u64 BnY  = *(const u64*)(cpy + idxB) ^ SGN;
    const u64 BnZ  = *(const u64*)(cpz + idxB) ^ SGN;
    const u64 BnVX = *(const u64*)(cvx + idxB) ^ SGN;
    const u64 BnVY = *(const u64*)(cvy + idxB) ^ SGN;
    const u64 BnVZ = *(const u64*)(cvz + idxB) ^ SGN;

    const u64 EPS2 = f2pack(1e-12f, 1e-12f);
    const u64 NKN  = f2pack(-6.0e6f, -6.0e6f);
    const u64 KNPS = f2pack( 6.0e5f,  6.0e5f);
    const u64 NETA = f2pack(-ETA, -ETA);

    u64 AfX = 0ull, AfY = 0ull, AfZ = 0ull;
    u64 BfX = 0ull, BfY = 0ull, BfZ = 0ull;

    const int colb = 2*tx;   // even float offset: A-pair at rb, B-pair at rb+2, mid from halves

    auto body = [&](u64 nX, u64 nY, u64 nZ, u64 nVX, u64 nVY, u64 nVZ,
                    u64& FX, u64& FY, u64& FZ,
                    u64 px_, u64 py_, u64 pz_, u64 wx_, u64 wy_, u64 wz_) {
        u64 ddx = f2add(px_, nX);
        u64 ddy = f2add(py_, nY);
        u64 ddz = f2add(pz_, nZ);
        u64 d2  = f2fma(ddx, ddx, f2fma(ddy, ddy, f2fma(ddz, ddz, EPS2)));
        float d2l, d2h; f2unpack(d2, d2l, d2h);
        float invl = rsqrtf(d2l), invh = rsqrtf(d2h);
        float rl = (d2l < 0.01f) ? fminf(invl, 1e4f) : 0.0f;   // contact gate folded into rdc
        float rh = (d2h < 0.01f) ? fminf(invh, 1e4f) : 0.0f;
        u64 inv  = f2pack(invl, invh);
        u64 rdc  = f2pack(rl, rh);
        u64 dist = f2mul(d2, inv);
        u64 dvx = f2add(wx_, nVX);
        u64 dvy = f2add(wy_, nVY);
        u64 dvz = f2add(wz_, nVZ);
        u64 dot = f2fma(dvx, ddx, f2fma(dvy, ddy, f2mul(dvz, ddz)));
        u64 s   = f2fma(NKN, dist, KNPS);
        s       = f2fma(f2mul(NETA, dot), rdc, s);
        u64 nc  = f2mul(s, rdc);             // = -coef ; ddx = -(xn-p) => product matches ref
        FX = f2fma(nc, ddx, FX);
        FY = f2fma(nc, ddy, FY);
        FZ = f2fma(nc, ddz, FZ);
    };

    #pragma unroll
    for (int m = 0; m < 2; ++m) {
        const float* px = posx + m*S;
        const float* py = posy + m*S;
        const float* pz = posz + m*S;
        const float* wx = m ? v1x : v0x;
        const float* wy = m ? v1y : v0y;
        const float* wz = m ? v1z : v0z;

        if (m) __syncthreads();
        #pragma unroll
        for (int i = 0; i < 8; ++i) {
            int e = tid + i*256;
            if (i < 7 || e < TILE_N) {
                int lz = e / PLANE;
                int r  = e - lz*PLANE;
                int ly = r / ROW;
                int lx = r - ly*ROW;
                int gz = (z0 + lz - 1) & (D-1);
                int gy = (y0 + ly - 1) & (D-1);
                int gx = (x0 + lx - 1) & (D-1);
                int g  = (gz*D + gy)*D + gx;
                sh[0][e] = px[g];  sh[1][e] = py[g];  sh[2][e] = pz[g];
                sh[3][e] = wx[g];  sh[4][e] = wy[g];  sh[5][e] = wz[g];
            }
        }
        __syncthreads();

        #pragma unroll
        for (int p = 0; p < 4; ++p) {          // local z planes 2tz+p ; A uses p=0..2, B uses p=1..3
            #pragma unroll
            for (int dy = 0; dy < 3; ++dy) {
                const int rb = (2*tz + p)*PLANE + (ty + dy)*ROW + colb;
                u64 Ax = *(const u64*)(&sh[0][rb]);
                u64 Ay = *(const u64*)(&sh[1][rb]);
                u64 Az = *(const u64*)(&sh[2][rb]);
                u64 Au = *(const u64*)(&sh[3][rb]);
                u64 Av = *(const u64*)(&sh[4][rb]);
                u64 Aw = *(const u64*)(&sh[5][rb]);
                u64 Bx = *(const u64*)(&sh[0][rb+2]);
                u64 By = *(const u64*)(&sh[1][rb+2]);
                u64 Bz = *(const u64*)(&sh[2][rb+2]);
                u64 Bu = *(const u64*)(&sh[3][rb+2]);
                u64 Bv = *(const u64*)(&sh[4][rb+2]);
                u64 Bw = *(const u64*)(&sh[5][rb+2]);
                u64 Mx = f2mid(Ax,Bx), My = f2mid(Ay,By), Mz = f2mid(Az,Bz);
                u64 Mu = f2mid(Au,Bu), Mv = f2mid(Av,Bv), Mw = f2mid(Aw,Bw);
                if (p < 3) {
                    body(AnX,AnY,AnZ,AnVX,AnVY,AnVZ, AfX,AfY,AfZ, Ax,Ay,Az,Au,Av,Aw);
                    body(AnX,AnY,AnZ,AnVX,AnVY,AnVZ, AfX,AfY,AfZ, Bx,By,Bz,Bu,Bv,Bw);
                    body(AnX,AnY,AnZ,AnVX,AnVY,AnVZ, AfX,AfY,AfZ, Mx,My,Mz,Mu,Mv,Mw);
                }
                if (p > 0) {
                    body(BnX,BnY,BnZ,BnVX,BnVY,BnVZ, BfX,BfY,BfZ, Ax,Ay,Az,Au,Av,Aw);
                    body(BnX,BnY,BnZ,BnVX,BnVY,BnVZ, BfX,BfY,BfZ, Bx,By,Bz,Bu,Bv,Bw);
                    body(BnX,BnY,BnZ,BnVX,BnVY,BnVZ, BfX,BfY,BfZ, Mx,My,Mz,Mu,Mv,Mw);
                }
            }
        }
    }

    // --- epilogue (per z-cell): reload centers from gmem, boundary + update ---
    const float KN = 6.0e6f;
    #pragma unroll
    for (int c = 0; c < 2; ++c) {
        const int idx = c ? idxB : idxA;
        const u64 FX = c ? BfX : AfX;
        const u64 FY = c ? BfY : AfY;
        const u64 FZ = c ? BfZ : AfZ;
        float xn0, xn1, yn0, yn1, zn0, zn1;
        float vx0, vx1, vy0, vy1, vz0, vz1;
        float fx0, fx1, fy0, fy1, fz0, fz1;
        float mk0, mk1;
        f2unpack(*(const u64*)(cpx + idx), xn0, xn1);
        f2unpack(*(const u64*)(cpy + idx), yn0, yn1);
        f2unpack(*(const u64*)(cpz + idx), zn0, zn1);
        f2unpack(*(const u64*)(cvx + idx), vx0, vx1);
        f2unpack(*(const u64*)(cvy + idx), vy0, vy1);
        f2unpack(*(const u64*)(cvz + idx), vz0, vz1);
        f2unpack(*(const u64*)(maskp + idx), mk0, mk1);
        f2unpack(FX, fx0, fx1);  f2unpack(FY, fy0, fy1);  f2unpack(FZ, fz0, fz1);

        float2 ox, oy, oz;
        {
            float fbx = 0.f, fby = 0.f, fbz = 0.f;
            if (xn0 > 0.1f && xn0 < 0.15f) fbx = fmaf(KN, 0.15f - xn0, -ETA*vx0);
            if (xn0 > 12.65f)              fbx = fmaf(-KN, xn0 - 12.65f, -ETA*vx0);
            if (yn0 > 0.1f && yn0 < 0.15f) fby = fmaf(KN, 0.15f - yn0, -ETA*vy0);
            if (yn0 > 12.65f)              fby = fmaf(-KN, yn0 - 12.65f, -ETA*vy0);
            if (zn0 > 0.1f && zn0 < 0.15f) fbz = fmaf(KN, 0.15f - zn0, -ETA*vz0);
            if (zn0 > 12.65f)              fbz = fmaf(-KN, zn0 - 12.65f, -ETA*vz0);
            ox.x = fmaf(DTPM*mk0, fbx - fx0, vx0);
            oy.x = fmaf(DTPM*mk0, fby - fy0, vy0);
            oz.x = fmaf(DTPM*mk0, GPM - fz0 + fbz, vz0);
        }
        {
            float fbx = 0.f, fby = 0.f, fbz = 0.f;
            if (xn1 > 0.1f && xn1 < 0.15f) fbx = fmaf(KN, 0.15f - xn1, -ETA*vx1);
            if (xn1 > 12.65f)              fbx = fmaf(-KN, xn1 - 12.65f, -ETA*vx1);
            if (yn1 > 0.1f && yn1 < 0.15f) fby = fmaf(KN, 0.15f - yn1, -ETA*vy1);
            if (yn1 > 12.65f)              fby = fmaf(-KN, yn1 - 12.65f, -ETA*vy1);
            if (zn1 > 0.1f && zn1 < 0.15f) fbz = fmaf(KN, 0.15f - zn1, -ETA*vz1);
            if (zn1 > 12.65f)              fbz = fmaf(-KN, zn1 - 12.65f, -ETA*vz1);
            ox.y = fmaf(DTPM*mk1, fbx - fx1, vx1);
            oy.y = fmaf(DTPM*mk1, fby - fy1, vy1);
            oz.y = fmaf(DTPM*mk1, GPM - fz1 + fbz, vz1);
        }
        *(float2*)(outx + idx) = ox;
        *(float2*)(outy + idx) = oy;
        *(float2*)(outz + idx) = oz;
    }
}

extern "C" void kernel_launch(void* const* d_in, const int* in_sizes, int n_in,
                              void* d_out, int out_size)
{
    const float* x  = (const float*)d_in[0];
    const float* y  = (const float*)d_in[1];
    const float* z  = (const float*)d_in[2];
    const float* vx = (const float*)d_in[3];
    const float* vy = (const float*)d_in[4];
    const float* vz = (const float*)d_in[5];
    const float* mk = (const float*)d_in[6];
    float* out = (float*)d_out;

    const double PM    = 4.0/3.0*3.1415*0.001*2700.0;
    const double alpha = 0.6931471805599453/3.141592653589793;
    const double gamma = alpha / sqrt(alpha*alpha + 1.0);
    const float ETA  = (float)(2.0 * gamma * sqrt(6.0e6 * PM));
    const float DTPM = (float)(1e-4 / PM);
    const float GPM  = (float)(-9.8 * PM);

    dim3 blk(16,8,2), grd(4,16,32);
    const int Sl = S;

    float* ox0 = out + 0*2*Sl;  float* ox1 = ox0 + Sl;
    float* oy0 = out + 1*2*Sl;  float* oy1 = oy0 + Sl;
    float* oz0 = out + 2*2*Sl;  float* oz1 = oz0 + Sl;

    // pass n = 0: all velocities original
    dem_pass<<<grd, blk>>>(x, y, z,
                           vx, vy, vz,
                           vx+Sl, vy+Sl, vz+Sl,
                           x, y, z,
                           vx, vy, vz,
                           mk,
                           ox0, oy0, oz0,
                           ETA, DTPM, GPM);

    // pass n = 1: layer-0 velocities are the just-updated outputs
    dem_pass<<<grd, blk>>>(x, y, z,
                           ox0, oy0, oz0,
                           vx+Sl, vy+Sl, vz+Sl,
                           x+Sl, y+Sl, z+Sl,
                           vx+Sl, vy+Sl, vz+Sl,
                           mk+Sl,
                           ox1, oy1, oz1,
                           ETA, DTPM, GPM);
}